// round 6
// baseline (speedup 1.0000x reference)
#include <cuda_runtime.h>
#include <cuda_bf16.h>
#include <cstdint>

#define N_NODES  200000
#define N_EDGES  800000
#define IN_CH    128
#define OUT_CH   64
#define MAX_DEG  4
#define N_GRAPHS 8192

#define SCAN_B   512
#define NB       ((N_NODES + SCAN_B - 1) / SCAN_B)   // 391

// ---------------- scratch (device globals; typed for alignment) ----------------
__device__ int    fpnn_stride;                        // 1 = int32 inputs, 2 = int64
__device__ int    fpnn_deg[N_NODES];
__device__ int    fpnn_off[N_NODES];
__device__ int    fpnn_fill[N_NODES];
__device__ int    fpnn_bsum[SCAN_B];
__device__ int    fpnn_csr[N_EDGES];
__device__ int    fpnn_cnt[MAX_DEG + 1];
__device__ int    fpnn_lists[(MAX_DEG + 1) * N_NODES];
__device__ float4 fpnn_agg4[(size_t)N_NODES * (IN_CH / 4)];   // 102.4 MB
__device__ float2 fpnn_pre2[(size_t)N_NODES * (OUT_CH / 2)];  // 51.2 MB

// ---------------- dtype detect: int64 inputs have zero high words ----------------
__global__ void fpnn_detect_kernel(const int* __restrict__ ei32) {
    if (threadIdx.x == 0 && blockIdx.x == 0) {
        int nz = 0;
        for (int i = 0; i < 64; i++) nz |= ei32[2 * i + 1];
        fpnn_stride = (nz == 0) ? 2 : 1;   // all odd words zero -> int64 layout
    }
}

// ---------------- zero init ----------------
__global__ void fpnn_zero_kernel() {
    int i = blockIdx.x * blockDim.x + threadIdx.x;
    if (i < N_NODES) fpnn_deg[i] = 0;
    if (i <= MAX_DEG) fpnn_cnt[i] = 0;
}

// ---------------- degree count ----------------
__global__ void fpnn_deg_kernel(const int* __restrict__ ei32) {
    int e = blockIdx.x * blockDim.x + threadIdx.x;
    if (e >= N_EDGES) return;
    int st = fpnn_stride;
    int dst = ei32[(size_t)st * (N_EDGES + e)];
    atomicAdd(&fpnn_deg[dst], 1);
}

// ---------------- scan A: per-block sums ----------------
__global__ void fpnn_scanA_kernel() {
    __shared__ int s[SCAN_B];
    int t = threadIdx.x;
    int i = blockIdx.x * SCAN_B + t;
    s[t] = (i < N_NODES) ? fpnn_deg[i] : 0;
    __syncthreads();
    for (int o = SCAN_B / 2; o > 0; o >>= 1) {
        if (t < o) s[t] += s[t + o];
        __syncthreads();
    }
    if (t == 0) fpnn_bsum[blockIdx.x] = s[0];
}

// ---------------- scan B: exclusive scan of block sums (1 block) ----------------
__global__ void fpnn_scanB_kernel() {
    __shared__ int s[SCAN_B];
    int t = threadIdx.x;
    int v = (t < NB) ? fpnn_bsum[t] : 0;
    s[t] = v;
    __syncthreads();
    for (int o = 1; o < SCAN_B; o <<= 1) {
        int add = (t >= o) ? s[t - o] : 0;
        __syncthreads();
        s[t] += add;
        __syncthreads();
    }
    if (t < NB) fpnn_bsum[t] = s[t] - v;   // exclusive
}

// ---------------- scan C: per-block exclusive scan + base -> offsets ----------------
__global__ void fpnn_scanC_kernel() {
    __shared__ int s[SCAN_B];
    int t = threadIdx.x;
    int i = blockIdx.x * SCAN_B + t;
    int v = (i < N_NODES) ? fpnn_deg[i] : 0;
    s[t] = v;
    __syncthreads();
    for (int o = 1; o < SCAN_B; o <<= 1) {
        int add = (t >= o) ? s[t - o] : 0;
        __syncthreads();
        s[t] += add;
        __syncthreads();
    }
    if (i < N_NODES) {
        fpnn_off[i] = s[t] - v + fpnn_bsum[blockIdx.x];
        fpnn_fill[i] = 0;
    }
}

// ---------------- fill CSR ----------------
__global__ void fpnn_fill_kernel(const int* __restrict__ ei32) {
    int e = blockIdx.x * blockDim.x + threadIdx.x;
    if (e >= N_EDGES) return;
    int st = fpnn_stride;
    int src = ei32[(size_t)st * e];
    int dst = ei32[(size_t)st * (N_EDGES + e)];
    int pos = fpnn_off[dst] + atomicAdd(&fpnn_fill[dst], 1);
    fpnn_csr[pos] = src;
}

// ---------------- aggregate (warp per node) + bucketize ----------------
__global__ void fpnn_agg_kernel(const float4* __restrict__ x4) {
    int w = (blockIdx.x * blockDim.x + threadIdx.x) >> 5;
    if (w >= N_NODES) return;
    int lane = threadIdx.x & 31;
    int deg = fpnn_deg[w];
    int off = fpnn_off[w];
    float4 acc = make_float4(0.f, 0.f, 0.f, 0.f);
    for (int i = 0; i < deg; i++) {
        int src = fpnn_csr[off + i];
        float4 v = x4[(size_t)src * 32 + lane];
        acc.x += v.x; acc.y += v.y; acc.z += v.z; acc.w += v.w;
    }
    fpnn_agg4[(size_t)w * 32 + lane] = acc;
    if (lane == 0) {
        int d = min(deg, MAX_DEG);
        int pos = atomicAdd(&fpnn_cnt[d], 1);
        fpnn_lists[d * N_NODES + pos] = w;
    }
}

// ---------------- node transform (tiled, smem weights + transposed features) ----
#define GX 296
#define M_TILE 32
__global__ void __launch_bounds__(256)
fpnn_gemm_kernel(const float4* __restrict__ x4,
                 const float4* __restrict__ Wlin4,
                 const float4* __restrict__ Wroot4) {
    __shared__ float2 w_s2[IN_CH * (OUT_CH / 2)];   // 32 KB
    __shared__ float4 f_s4[IN_CH * (M_TILE / 4)];   // 16 KB

    int d = blockIdx.y;
    int count = fpnn_cnt[d];
    const int* list = fpnn_lists + d * N_NODES;

    int tid = threadIdx.x;
    int nq = tid & 7;
    int jp = tid >> 3;
    int nload = tid >> 3;        // node slot this thread loads (0..31)
    int kt = tid & 7;            // k-sixteenth for loading

    float* f_scalar = (float*)f_s4;

    for (int tile = blockIdx.x; tile * M_TILE < count; tile += GX) {
        float acc[4][2];
#pragma unroll
        for (int i = 0; i < 4; i++) { acc[i][0] = 0.f; acc[i][1] = 0.f; }

#pragma unroll
        for (int pass = 0; pass < 2; pass++) {
            const float4* Wsrc4 = (pass == 0 ? Wlin4 : Wroot4) + (size_t)d * (IN_CH * OUT_CH / 4);
#pragma unroll
            for (int j = 0; j < 8; j++) {
                int flat = tid + j * 256;            // float4 index
                float4 v = Wsrc4[flat];
                int k = flat >> 4;                   // 16 float4 per k-row
                int c4 = flat & 15;
                w_s2[k * 32 + 2 * c4]     = make_float2(v.x, v.y);
                w_s2[k * 32 + 2 * c4 + 1] = make_float2(v.z, v.w);
            }

            int nidx = tile * M_TILE + nload;
            if (nidx < count) {
                int n = list[nidx];
                const float4* row4 = (pass == 0) ? (fpnn_agg4 + (size_t)n * 32)
                                                 : (x4 + (size_t)n * 32);
#pragma unroll
                for (int q = 0; q < 4; q++) {
                    float4 v = row4[kt * 4 + q];
                    int kb = kt * 16 + q * 4;
                    f_scalar[(kb + 0) * M_TILE + nload] = v.x;
                    f_scalar[(kb + 1) * M_TILE + nload] = v.y;
                    f_scalar[(kb + 2) * M_TILE + nload] = v.z;
                    f_scalar[(kb + 3) * M_TILE + nload] = v.w;
                }
            } else {
#pragma unroll
                for (int q = 0; q < 4; q++) {
                    int kb = kt * 16 + q * 4;
                    f_scalar[(kb + 0) * M_TILE + nload] = 0.f;
                    f_scalar[(kb + 1) * M_TILE + nload] = 0.f;
                    f_scalar[(kb + 2) * M_TILE + nload] = 0.f;
                    f_scalar[(kb + 3) * M_TILE + nload] = 0.f;
                }
            }
            __syncthreads();

#pragma unroll 4
            for (int k = 0; k < IN_CH; k++) {
                float4 f = f_s4[k * 8 + nq];
                float2 w = w_s2[k * 32 + jp];
                acc[0][0] += f.x * w.x; acc[0][1] += f.x * w.y;
                acc[1][0] += f.y * w.x; acc[1][1] += f.y * w.y;
                acc[2][0] += f.z * w.x; acc[2][1] += f.z * w.y;
                acc[3][0] += f.w * w.x; acc[3][1] += f.w * w.y;
            }
            __syncthreads();
        }

#pragma unroll
        for (int i = 0; i < 4; i++) {
            int nidx = tile * M_TILE + nq * 4 + i;
            if (nidx < count) {
                int n = list[nidx];
                fpnn_pre2[(size_t)n * 32 + jp] = make_float2(acc[i][0], acc[i][1]);
            }
        }
    }
}

// ---------------- relu + softmax, thread per node, in place ----------------
__global__ void fpnn_softmax_kernel() {
    int n = blockIdx.x * blockDim.x + threadIdx.x;
    if (n >= N_NODES) return;
    float2 row[32];
    float m = 0.f;   // relu floor: max >= 0
#pragma unroll
    for (int j = 0; j < 32; j++) {
        float2 v = fpnn_pre2[(size_t)n * 32 + j];
        v.x = fmaxf(v.x, 0.f);
        v.y = fmaxf(v.y, 0.f);
        m = fmaxf(m, fmaxf(v.x, v.y));
        row[j] = v;
    }
    float s = 0.f;
#pragma unroll
    for (int j = 0; j < 32; j++) {
        row[j].x = __expf(row[j].x - m);
        row[j].y = __expf(row[j].y - m);
        s += row[j].x + row[j].y;
    }
    float inv = 1.0f / s;
#pragma unroll
    for (int j = 0; j < 32; j++) {
        fpnn_pre2[(size_t)n * 32 + j] = make_float2(row[j].x * inv, row[j].y * inv);
    }
}

// ---------------- pool: thread per graph, binary search over sorted batch ----
__global__ void fpnn_pool_kernel(const int* __restrict__ b32, float* __restrict__ out) {
    int g = blockIdx.x * blockDim.x + threadIdx.x;
    if (g >= N_GRAPHS) return;
    int st = fpnn_stride;

    int lo = 0, hi = N_NODES;
    while (lo < hi) { int mid = (lo + hi) >> 1; if (b32[(size_t)st * mid] < g) lo = mid + 1; else hi = mid; }
    int start = lo;
    hi = N_NODES;
    while (lo < hi) { int mid = (lo + hi) >> 1; if (b32[(size_t)st * mid] < g + 1) lo = mid + 1; else hi = mid; }
    int end = lo;

    float2 acc[32];
#pragma unroll
    for (int j = 0; j < 32; j++) acc[j] = make_float2(0.f, 0.f);

    for (int n = start; n < end; n++) {
#pragma unroll
        for (int j = 0; j < 32; j++) {
            float2 v = fpnn_pre2[(size_t)n * 32 + j];
            acc[j].x += v.x;
            acc[j].y += v.y;
        }
    }
#pragma unroll
    for (int j = 0; j < 32; j++) {
        out[(size_t)g * OUT_CH + 2 * j]     = acc[j].x;
        out[(size_t)g * OUT_CH + 2 * j + 1] = acc[j].y;
    }
}

// ---------------- launch: SIZE-BASED input dispatch (order-proof) ----------------
extern "C" void kernel_launch(void* const* d_in, const int* in_sizes, int n_in,
                              void* d_out, int out_size) {
    // Identify inputs by element count (dtype-invariant):
    //   x = 25,600,000 ; edge_index = 1,600,000 ; batch = 200,000 ; W = 40,960 each
    const float* x = 0; const int* ei32 = 0; const int* b32 = 0;
    const float* Wlin = 0; const float* Wroot = 0;
    for (int i = 0; i < n_in; i++) {
        int s = in_sizes[i];
        if      (s == N_NODES * IN_CH)        x    = (const float*)d_in[i];
        else if (s == 2 * N_EDGES)            ei32 = (const int*)d_in[i];
        else if (s == N_NODES)                b32  = (const int*)d_in[i];
        else if (s == (MAX_DEG + 1) * IN_CH * OUT_CH) {
            if (!Wlin) Wlin = (const float*)d_in[i];
            else       Wroot = (const float*)d_in[i];
        }
    }
    if (!x)     x     = (const float*)d_in[0];
    if (!ei32)  ei32  = (const int*)d_in[1];
    if (!b32)   b32   = (const int*)d_in[2];
    if (!Wlin)  Wlin  = (const float*)d_in[3];
    if (!Wroot) Wroot = (const float*)d_in[4];
    float* out = (float*)d_out;

    fpnn_detect_kernel<<<1, 32>>>(ei32);
    fpnn_zero_kernel<<<(N_NODES + 255) / 256, 256>>>();
    fpnn_deg_kernel<<<(N_EDGES + 255) / 256, 256>>>(ei32);
    fpnn_scanA_kernel<<<NB, SCAN_B>>>();
    fpnn_scanB_kernel<<<1, SCAN_B>>>();
    fpnn_scanC_kernel<<<NB, SCAN_B>>>();
    fpnn_fill_kernel<<<(N_EDGES + 255) / 256, 256>>>(ei32);
    fpnn_agg_kernel<<<(N_NODES * 32 + 255) / 256, 256>>>((const float4*)x);
    fpnn_gemm_kernel<<<dim3(GX, MAX_DEG + 1), 256>>>((const float4*)x,
                                                     (const float4*)Wlin,
                                                     (const float4*)Wroot);
    fpnn_softmax_kernel<<<(N_NODES + 255) / 256, 256>>>();
    fpnn_pool_kernel<<<(N_GRAPHS + 127) / 128, 128>>>(b32, out);
}

// round 7
// speedup vs baseline: 1.1435x; 1.1435x over previous
#include <cuda_runtime.h>
#include <cuda_bf16.h>
#include <cstdint>

#define N_NODES  200000
#define N_EDGES  800000
#define IN_CH    128
#define OUT_CH   64
#define MAX_DEG  4
#define N_GRAPHS 8192

#define SCAN_B   512
#define NB       ((N_NODES + SCAN_B - 1) / SCAN_B)   // 391

// ---------------- scratch (device globals; typed for alignment) ----------------
__device__ int    fpnn_stride;                        // 1 = int32 inputs, 2 = int64
__device__ int    fpnn_deg[N_NODES];
__device__ int    fpnn_off[N_NODES];
__device__ int    fpnn_fill[N_NODES];
__device__ int    fpnn_bsum[SCAN_B];
__device__ int    fpnn_csr[N_EDGES];
__device__ int    fpnn_cnt[MAX_DEG + 1];
__device__ int    fpnn_lists[(MAX_DEG + 1) * N_NODES];
__device__ float4 fpnn_agg4[(size_t)N_NODES * (IN_CH / 4)];   // 102.4 MB
__device__ float2 fpnn_pre2[(size_t)N_NODES * (OUT_CH / 2)];  // 51.2 MB

// ---------------- dtype detect: int64 inputs have zero high words ----------------
__global__ void fpnn_detect_kernel(const int* __restrict__ ei32) {
    if (threadIdx.x == 0 && blockIdx.x == 0) {
        int nz = 0;
        for (int i = 0; i < 64; i++) nz |= ei32[2 * i + 1];
        fpnn_stride = (nz == 0) ? 2 : 1;   // all odd words zero -> int64 layout
    }
}

// ---------------- zero init (scratch + output) ----------------
__global__ void fpnn_zero_kernel(float4* __restrict__ out4) {
    int i = blockIdx.x * blockDim.x + threadIdx.x;
    if (i < N_NODES) fpnn_deg[i] = 0;
    if (i <= MAX_DEG) fpnn_cnt[i] = 0;
    if (i < N_GRAPHS * OUT_CH / 4) out4[i] = make_float4(0.f, 0.f, 0.f, 0.f);
}

// ---------------- degree count ----------------
__global__ void fpnn_deg_kernel(const int* __restrict__ ei32) {
    int e = blockIdx.x * blockDim.x + threadIdx.x;
    if (e >= N_EDGES) return;
    int st = fpnn_stride;
    int dst = ei32[(size_t)st * (N_EDGES + e)];
    atomicAdd(&fpnn_deg[dst], 1);
}

// ---------------- scan A: per-block sums ----------------
__global__ void fpnn_scanA_kernel() {
    __shared__ int s[SCAN_B];
    int t = threadIdx.x;
    int i = blockIdx.x * SCAN_B + t;
    s[t] = (i < N_NODES) ? fpnn_deg[i] : 0;
    __syncthreads();
    for (int o = SCAN_B / 2; o > 0; o >>= 1) {
        if (t < o) s[t] += s[t + o];
        __syncthreads();
    }
    if (t == 0) fpnn_bsum[blockIdx.x] = s[0];
}

// ---------------- scan B: exclusive scan of block sums (1 block) ----------------
__global__ void fpnn_scanB_kernel() {
    __shared__ int s[SCAN_B];
    int t = threadIdx.x;
    int v = (t < NB) ? fpnn_bsum[t] : 0;
    s[t] = v;
    __syncthreads();
    for (int o = 1; o < SCAN_B; o <<= 1) {
        int add = (t >= o) ? s[t - o] : 0;
        __syncthreads();
        s[t] += add;
        __syncthreads();
    }
    if (t < NB) fpnn_bsum[t] = s[t] - v;   // exclusive
}

// ---------------- scan C: per-block exclusive scan + base -> offsets ----------------
__global__ void fpnn_scanC_kernel() {
    __shared__ int s[SCAN_B];
    int t = threadIdx.x;
    int i = blockIdx.x * SCAN_B + t;
    int v = (i < N_NODES) ? fpnn_deg[i] : 0;
    s[t] = v;
    __syncthreads();
    for (int o = 1; o < SCAN_B; o <<= 1) {
        int add = (t >= o) ? s[t - o] : 0;
        __syncthreads();
        s[t] += add;
        __syncthreads();
    }
    if (i < N_NODES) {
        fpnn_off[i] = s[t] - v + fpnn_bsum[blockIdx.x];
        fpnn_fill[i] = 0;
    }
}

// ---------------- fill CSR ----------------
__global__ void fpnn_fill_kernel(const int* __restrict__ ei32) {
    int e = blockIdx.x * blockDim.x + threadIdx.x;
    if (e >= N_EDGES) return;
    int st = fpnn_stride;
    int src = ei32[(size_t)st * e];
    int dst = ei32[(size_t)st * (N_EDGES + e)];
    int pos = fpnn_off[dst] + atomicAdd(&fpnn_fill[dst], 1);
    fpnn_csr[pos] = src;
}

// ---------------- aggregate (warp per node) + bucketize ----------------
__global__ void fpnn_agg_kernel(const float4* __restrict__ x4) {
    int w = (blockIdx.x * blockDim.x + threadIdx.x) >> 5;
    if (w >= N_NODES) return;
    int lane = threadIdx.x & 31;
    int deg = fpnn_deg[w];
    int off = fpnn_off[w];
    float4 acc = make_float4(0.f, 0.f, 0.f, 0.f);
    for (int i = 0; i < deg; i++) {
        int src = fpnn_csr[off + i];
        float4 v = x4[(size_t)src * 32 + lane];
        acc.x += v.x; acc.y += v.y; acc.z += v.z; acc.w += v.w;
    }
    fpnn_agg4[(size_t)w * 32 + lane] = acc;
    if (lane == 0) {
        int d = min(deg, MAX_DEG);
        int pos = atomicAdd(&fpnn_cnt[d], 1);
        fpnn_lists[d * N_NODES + pos] = w;
    }
}

// ---------------- node transform: pre = agg@Wlin[d] + x@Wroot[d], fused passes ---
// Static smem: two transposed feature tiles (agg, x), 16 KB each.
// Weights streamed via LDG (64 KB per bucket, L1-resident after first tile).
// Thread: nq = tid&7 -> nodes [nq*4..nq*4+3]; jp = tid>>3 -> channels {2jp,2jp+1}.
#define GX 296
#define M_TILE 32
__global__ void __launch_bounds__(256)
fpnn_gemm_kernel(const float4* __restrict__ x4,
                 const float* __restrict__ Wlin,
                 const float* __restrict__ Wroot) {
    __shared__ float4 fa4[IN_CH * (M_TILE / 4)];   // agg tile, 16 KB
    __shared__ float4 fx4[IN_CH * (M_TILE / 4)];   // x tile, 16 KB

    int d = blockIdx.y;
    int count = fpnn_cnt[d];
    const int* list = fpnn_lists + d * N_NODES;
    const float* wl = Wlin  + (size_t)d * IN_CH * OUT_CH;
    const float* wr = Wroot + (size_t)d * IN_CH * OUT_CH;

    int tid = threadIdx.x;
    int nq = tid & 7;
    int jp = tid >> 3;
    int nload = tid >> 3;        // node slot this thread loads (0..31)
    int kt = tid & 7;            // k-sixteenth for loading

    float* fa = (float*)fa4;
    float* fx = (float*)fx4;

    for (int tile = blockIdx.x; tile * M_TILE < count; tile += GX) {
        float acc[4][2];
#pragma unroll
        for (int i = 0; i < 4; i++) { acc[i][0] = 0.f; acc[i][1] = 0.f; }

        // load both feature tiles, transposed: f[k*32 + node]
        int nidx = tile * M_TILE + nload;
        if (nidx < count) {
            int n = list[nidx];
            const float4* ra = fpnn_agg4 + (size_t)n * 32;
            const float4* rx = x4 + (size_t)n * 32;
#pragma unroll
            for (int q = 0; q < 4; q++) {
                float4 va = ra[kt * 4 + q];
                float4 vx = rx[kt * 4 + q];
                int kb = kt * 16 + q * 4;
                fa[(kb + 0) * M_TILE + nload] = va.x;
                fa[(kb + 1) * M_TILE + nload] = va.y;
                fa[(kb + 2) * M_TILE + nload] = va.z;
                fa[(kb + 3) * M_TILE + nload] = va.w;
                fx[(kb + 0) * M_TILE + nload] = vx.x;
                fx[(kb + 1) * M_TILE + nload] = vx.y;
                fx[(kb + 2) * M_TILE + nload] = vx.z;
                fx[(kb + 3) * M_TILE + nload] = vx.w;
            }
        } else {
#pragma unroll
            for (int q = 0; q < 4; q++) {
                int kb = kt * 16 + q * 4;
#pragma unroll
                for (int r = 0; r < 4; r++) {
                    fa[(kb + r) * M_TILE + nload] = 0.f;
                    fx[(kb + r) * M_TILE + nload] = 0.f;
                }
            }
        }
        __syncthreads();

#pragma unroll 4
        for (int k = 0; k < IN_CH; k++) {
            float4 a  = fa4[k * 8 + nq];
            float4 xv = fx4[k * 8 + nq];
            float2 w1 = *(const float2*)(wl + k * OUT_CH + jp * 2);
            float2 w2 = *(const float2*)(wr + k * OUT_CH + jp * 2);
            acc[0][0] += a.x * w1.x;  acc[0][1] += a.x * w1.y;
            acc[1][0] += a.y * w1.x;  acc[1][1] += a.y * w1.y;
            acc[2][0] += a.z * w1.x;  acc[2][1] += a.z * w1.y;
            acc[3][0] += a.w * w1.x;  acc[3][1] += a.w * w1.y;
            acc[0][0] += xv.x * w2.x; acc[0][1] += xv.x * w2.y;
            acc[1][0] += xv.y * w2.x; acc[1][1] += xv.y * w2.y;
            acc[2][0] += xv.z * w2.x; acc[2][1] += xv.z * w2.y;
            acc[3][0] += xv.w * w2.x; acc[3][1] += xv.w * w2.y;
        }
        __syncthreads();

#pragma unroll
        for (int i = 0; i < 4; i++) {
            int sidx = tile * M_TILE + nq * 4 + i;
            if (sidx < count) {
                int n = list[sidx];
                fpnn_pre2[(size_t)n * 32 + jp] = make_float2(acc[i][0], acc[i][1]);
            }
        }
    }
}

// ---------------- fused relu + softmax + pool (warp per 8 sorted nodes) ---------
#define NODES_PER_WARP 8
__global__ void fpnn_spool_kernel(const int* __restrict__ b32,
                                  float* __restrict__ out) {
    int warp = (blockIdx.x * blockDim.x + threadIdx.x) >> 5;
    int lane = threadIdx.x & 31;
    int n0 = warp * NODES_PER_WARP;
    if (n0 >= N_NODES) return;
    int st = fpnn_stride;

    float2 acc = make_float2(0.f, 0.f);
    int gcur = b32[(size_t)st * n0];

#pragma unroll
    for (int i = 0; i < NODES_PER_WARP; i++) {
        int n = n0 + i;
        int g = b32[(size_t)st * n];
        if (g != gcur) {
            atomicAdd(out + (size_t)gcur * OUT_CH + 2 * lane,     acc.x);
            atomicAdd(out + (size_t)gcur * OUT_CH + 2 * lane + 1, acc.y);
            acc = make_float2(0.f, 0.f);
            gcur = g;
        }
        float2 v = fpnn_pre2[(size_t)n * 32 + lane];
        v.x = fmaxf(v.x, 0.f);
        v.y = fmaxf(v.y, 0.f);
        float m = fmaxf(v.x, v.y);
#pragma unroll
        for (int s = 16; s; s >>= 1) m = fmaxf(m, __shfl_xor_sync(0xffffffffu, m, s));
        float ex = __expf(v.x - m), ey = __expf(v.y - m);
        float s = ex + ey;
#pragma unroll
        for (int ss = 16; ss; ss >>= 1) s += __shfl_xor_sync(0xffffffffu, s, ss);
        float inv = 1.0f / s;
        acc.x += ex * inv;
        acc.y += ey * inv;
    }
    atomicAdd(out + (size_t)gcur * OUT_CH + 2 * lane,     acc.x);
    atomicAdd(out + (size_t)gcur * OUT_CH + 2 * lane + 1, acc.y);
}

// ---------------- launch: SIZE-BASED input dispatch (order-proof) ----------------
extern "C" void kernel_launch(void* const* d_in, const int* in_sizes, int n_in,
                              void* d_out, int out_size) {
    const float* x = 0; const int* ei32 = 0; const int* b32 = 0;
    const float* Wlin = 0; const float* Wroot = 0;
    for (int i = 0; i < n_in; i++) {
        int s = in_sizes[i];
        if      (s == N_NODES * IN_CH)        x    = (const float*)d_in[i];
        else if (s == 2 * N_EDGES)            ei32 = (const int*)d_in[i];
        else if (s == N_NODES)                b32  = (const int*)d_in[i];
        else if (s == (MAX_DEG + 1) * IN_CH * OUT_CH) {
            if (!Wlin) Wlin = (const float*)d_in[i];
            else       Wroot = (const float*)d_in[i];
        }
    }
    if (!x)     x     = (const float*)d_in[0];
    if (!ei32)  ei32  = (const int*)d_in[1];
    if (!b32)   b32   = (const int*)d_in[2];
    if (!Wlin)  Wlin  = (const float*)d_in[3];
    if (!Wroot) Wroot = (const float*)d_in[4];
    float* out = (float*)d_out;

    fpnn_detect_kernel<<<1, 32>>>(ei32);
    fpnn_zero_kernel<<<(N_NODES + 255) / 256, 256>>>((float4*)out);
    fpnn_deg_kernel<<<(N_EDGES + 255) / 256, 256>>>(ei32);
    fpnn_scanA_kernel<<<NB, SCAN_B>>>();
    fpnn_scanB_kernel<<<1, SCAN_B>>>();
    fpnn_scanC_kernel<<<NB, SCAN_B>>>();
    fpnn_fill_kernel<<<(N_EDGES + 255) / 256, 256>>>(ei32);
    fpnn_agg_kernel<<<(N_NODES * 32 + 255) / 256, 256>>>((const float4*)x);
    fpnn_gemm_kernel<<<dim3(GX, MAX_DEG + 1), 256>>>((const float4*)x, Wlin, Wroot);
    fpnn_spool_kernel<<<(N_NODES / NODES_PER_WARP * 32 + 255) / 256, 256>>>(b32, out);
}

// round 8
// speedup vs baseline: 1.2560x; 1.0983x over previous
#include <cuda_runtime.h>
#include <cuda_bf16.h>
#include <cstdint>

#define N_NODES  200000
#define N_EDGES  800000
#define IN_CH    128
#define OUT_CH   64
#define MAX_DEG  4
#define N_GRAPHS 8192

#define SCAN_B   512
#define NB       ((N_NODES + SCAN_B - 1) / SCAN_B)   // 391

// ---------------- scratch (device globals; typed for alignment) ----------------
__device__ int    fpnn_stride;                        // 1 = int32 inputs, 2 = int64
__device__ int    fpnn_deg[N_NODES];
__device__ int    fpnn_off[N_NODES];
__device__ int    fpnn_fill[N_NODES];
__device__ int    fpnn_bsum[SCAN_B];
__device__ int    fpnn_csr[N_EDGES];
__device__ int    fpnn_cnt[MAX_DEG + 1];
__device__ int    fpnn_lists[(MAX_DEG + 1) * N_NODES];
__device__ float2 fpnn_pre2[(size_t)N_NODES * (OUT_CH / 2)];  // 51.2 MB

// ---------------- dtype detect: int64 inputs have zero high words ----------------
__global__ void fpnn_detect_kernel(const int* __restrict__ ei32) {
    if (threadIdx.x == 0 && blockIdx.x == 0) {
        int nz = 0;
        for (int i = 0; i < 64; i++) nz |= ei32[2 * i + 1];
        fpnn_stride = (nz == 0) ? 2 : 1;   // all odd words zero -> int64 layout
    }
}

// ---------------- zero init (scratch + output) ----------------
__global__ void fpnn_zero_kernel(float4* __restrict__ out4) {
    int i = blockIdx.x * blockDim.x + threadIdx.x;
    if (i < N_NODES) fpnn_deg[i] = 0;
    if (i <= MAX_DEG) fpnn_cnt[i] = 0;
    if (i < N_GRAPHS * OUT_CH / 4) out4[i] = make_float4(0.f, 0.f, 0.f, 0.f);
}

// ---------------- degree count ----------------
__global__ void fpnn_deg_kernel(const int* __restrict__ ei32) {
    int e = blockIdx.x * blockDim.x + threadIdx.x;
    if (e >= N_EDGES) return;
    int st = fpnn_stride;
    int dst = ei32[(size_t)st * (N_EDGES + e)];
    atomicAdd(&fpnn_deg[dst], 1);
}

// ---------------- scan A: per-block sums ----------------
__global__ void fpnn_scanA_kernel() {
    __shared__ int s[SCAN_B];
    int t = threadIdx.x;
    int i = blockIdx.x * SCAN_B + t;
    s[t] = (i < N_NODES) ? fpnn_deg[i] : 0;
    __syncthreads();
    for (int o = SCAN_B / 2; o > 0; o >>= 1) {
        if (t < o) s[t] += s[t + o];
        __syncthreads();
    }
    if (t == 0) fpnn_bsum[blockIdx.x] = s[0];
}

// ---------------- scan B: exclusive scan of block sums (1 block) ----------------
__global__ void fpnn_scanB_kernel() {
    __shared__ int s[SCAN_B];
    int t = threadIdx.x;
    int v = (t < NB) ? fpnn_bsum[t] : 0;
    s[t] = v;
    __syncthreads();
    for (int o = 1; o < SCAN_B; o <<= 1) {
        int add = (t >= o) ? s[t - o] : 0;
        __syncthreads();
        s[t] += add;
        __syncthreads();
    }
    if (t < NB) fpnn_bsum[t] = s[t] - v;   // exclusive
}

// ---------------- scan C: per-block exclusive scan + base -> offsets ----------------
__global__ void fpnn_scanC_kernel() {
    __shared__ int s[SCAN_B];
    int t = threadIdx.x;
    int i = blockIdx.x * SCAN_B + t;
    int v = (i < N_NODES) ? fpnn_deg[i] : 0;
    s[t] = v;
    __syncthreads();
    for (int o = 1; o < SCAN_B; o <<= 1) {
        int add = (t >= o) ? s[t - o] : 0;
        __syncthreads();
        s[t] += add;
        __syncthreads();
    }
    if (i < N_NODES) {
        fpnn_off[i] = s[t] - v + fpnn_bsum[blockIdx.x];
        fpnn_fill[i] = 0;
    }
}

// ---------------- fill CSR ----------------
__global__ void fpnn_fill_kernel(const int* __restrict__ ei32) {
    int e = blockIdx.x * blockDim.x + threadIdx.x;
    if (e >= N_EDGES) return;
    int st = fpnn_stride;
    int src = ei32[(size_t)st * e];
    int dst = ei32[(size_t)st * (N_EDGES + e)];
    int pos = fpnn_off[dst] + atomicAdd(&fpnn_fill[dst], 1);
    fpnn_csr[pos] = src;
}

// ---------------- bucketize nodes by clamped in-degree ----------------
__global__ void fpnn_bucket_kernel() {
    int n = blockIdx.x * blockDim.x + threadIdx.x;
    if (n >= N_NODES) return;
    int d = min(fpnn_deg[n], MAX_DEG);
    int pos = atomicAdd(&fpnn_cnt[d], 1);
    fpnn_lists[d * N_NODES + pos] = n;
}

// ---------------- fused aggregate + node transform ------------------------------
// pre = (sum_{src in N(n)} x[src]) @ Wlin[d] + x[n] @ Wroot[d]
// The agg tile is built IN the loader by CSR gather (no agg intermediate).
// Block: 256 threads, tile = 32 nodes x 64 channels.
// Loader thread (nload = tid>>3, kt = tid&7): chunk kt (16 floats) of node nload.
// Compute thread (nq = tid&7, jp = tid>>3): nodes nq*4..nq*4+3, channels {2jp,2jp+1}.
#define GX 296
#define M_TILE 32
__global__ void __launch_bounds__(256)
fpnn_gemm_kernel(const float4* __restrict__ x4,
                 const float* __restrict__ Wlin,
                 const float* __restrict__ Wroot) {
    __shared__ float4 fa4[IN_CH * (M_TILE / 4)];   // gathered agg tile, 16 KB
    __shared__ float4 fx4[IN_CH * (M_TILE / 4)];   // x tile, 16 KB

    int d = blockIdx.y;
    int count = fpnn_cnt[d];
    const int* list = fpnn_lists + d * N_NODES;
    const float* wl = Wlin  + (size_t)d * IN_CH * OUT_CH;
    const float* wr = Wroot + (size_t)d * IN_CH * OUT_CH;

    int tid = threadIdx.x;
    int nq = tid & 7;
    int jp = tid >> 3;
    int nload = tid >> 3;
    int kt = tid & 7;

    float* fa = (float*)fa4;
    float* fx = (float*)fx4;

    for (int tile = blockIdx.x; tile * M_TILE < count; tile += GX) {
        float acc[4][2];
#pragma unroll
        for (int i = 0; i < 4; i++) { acc[i][0] = 0.f; acc[i][1] = 0.f; }

        int nidx = tile * M_TILE + nload;
        if (nidx < count) {
            int n = list[nidx];
            int deg = fpnn_deg[n];
            int off = fpnn_off[n];

            // gather-aggregate chunk kt of all neighbors
            float4 s0 = make_float4(0.f,0.f,0.f,0.f), s1 = s0, s2 = s0, s3 = s0;
            for (int i = 0; i < deg; i++) {
                int src = fpnn_csr[off + i];
                const float4* r = x4 + (size_t)src * 32 + kt * 4;
                float4 a = r[0], b = r[1], c = r[2], e = r[3];
                s0.x += a.x; s0.y += a.y; s0.z += a.z; s0.w += a.w;
                s1.x += b.x; s1.y += b.y; s1.z += b.z; s1.w += b.w;
                s2.x += c.x; s2.y += c.y; s2.z += c.z; s2.w += c.w;
                s3.x += e.x; s3.y += e.y; s3.z += e.z; s3.w += e.w;
            }
            const float4* rx = x4 + (size_t)n * 32 + kt * 4;
            float4 v0 = rx[0], v1 = rx[1], v2 = rx[2], v3 = rx[3];

            int kb = kt * 16;
            float4 sv[4] = {s0, s1, s2, s3};
            float4 xv[4] = {v0, v1, v2, v3};
#pragma unroll
            for (int q = 0; q < 4; q++) {
                fa[(kb + 4*q + 0) * M_TILE + nload] = sv[q].x;
                fa[(kb + 4*q + 1) * M_TILE + nload] = sv[q].y;
                fa[(kb + 4*q + 2) * M_TILE + nload] = sv[q].z;
                fa[(kb + 4*q + 3) * M_TILE + nload] = sv[q].w;
                fx[(kb + 4*q + 0) * M_TILE + nload] = xv[q].x;
                fx[(kb + 4*q + 1) * M_TILE + nload] = xv[q].y;
                fx[(kb + 4*q + 2) * M_TILE + nload] = xv[q].z;
                fx[(kb + 4*q + 3) * M_TILE + nload] = xv[q].w;
            }
        } else {
            int kb = kt * 16;
#pragma unroll
            for (int r = 0; r < 16; r++) {
                fa[(kb + r) * M_TILE + nload] = 0.f;
                fx[(kb + r) * M_TILE + nload] = 0.f;
            }
        }
        __syncthreads();

#pragma unroll 4
        for (int k = 0; k < IN_CH; k++) {
            float4 a  = fa4[k * 8 + nq];
            float4 xv = fx4[k * 8 + nq];
            float2 w1 = *(const float2*)(wl + k * OUT_CH + jp * 2);
            float2 w2 = *(const float2*)(wr + k * OUT_CH + jp * 2);
            acc[0][0] += a.x * w1.x;  acc[0][1] += a.x * w1.y;
            acc[1][0] += a.y * w1.x;  acc[1][1] += a.y * w1.y;
            acc[2][0] += a.z * w1.x;  acc[2][1] += a.z * w1.y;
            acc[3][0] += a.w * w1.x;  acc[3][1] += a.w * w1.y;
            acc[0][0] += xv.x * w2.x; acc[0][1] += xv.x * w2.y;
            acc[1][0] += xv.y * w2.x; acc[1][1] += xv.y * w2.y;
            acc[2][0] += xv.z * w2.x; acc[2][1] += xv.z * w2.y;
            acc[3][0] += xv.w * w2.x; acc[3][1] += xv.w * w2.y;
        }
        __syncthreads();

#pragma unroll
        for (int i = 0; i < 4; i++) {
            int sidx = tile * M_TILE + nq * 4 + i;
            if (sidx < count) {
                int n = list[sidx];
                fpnn_pre2[(size_t)n * 32 + jp] = make_float2(acc[i][0], acc[i][1]);
            }
        }
    }
}

// ---------------- fused relu + softmax + pool (warp per 8 sorted nodes) ---------
#define NODES_PER_WARP 8
__global__ void fpnn_spool_kernel(const int* __restrict__ b32,
                                  float* __restrict__ out) {
    int warp = (blockIdx.x * blockDim.x + threadIdx.x) >> 5;
    int lane = threadIdx.x & 31;
    int n0 = warp * NODES_PER_WARP;
    if (n0 >= N_NODES) return;
    int st = fpnn_stride;

    float2 acc = make_float2(0.f, 0.f);
    int gcur = b32[(size_t)st * n0];

#pragma unroll
    for (int i = 0; i < NODES_PER_WARP; i++) {
        int n = n0 + i;
        int g = b32[(size_t)st * n];
        if (g != gcur) {
            atomicAdd(out + (size_t)gcur * OUT_CH + 2 * lane,     acc.x);
            atomicAdd(out + (size_t)gcur * OUT_CH + 2 * lane + 1, acc.y);
            acc = make_float2(0.f, 0.f);
            gcur = g;
        }
        float2 v = fpnn_pre2[(size_t)n * 32 + lane];
        v.x = fmaxf(v.x, 0.f);
        v.y = fmaxf(v.y, 0.f);
        float m = fmaxf(v.x, v.y);
#pragma unroll
        for (int s = 16; s; s >>= 1) m = fmaxf(m, __shfl_xor_sync(0xffffffffu, m, s));
        float ex = __expf(v.x - m), ey = __expf(v.y - m);
        float s = ex + ey;
#pragma unroll
        for (int ss = 16; ss; ss >>= 1) s += __shfl_xor_sync(0xffffffffu, s, ss);
        float inv = 1.0f / s;
        acc.x += ex * inv;
        acc.y += ey * inv;
    }
    atomicAdd(out + (size_t)gcur * OUT_CH + 2 * lane,     acc.x);
    atomicAdd(out + (size_t)gcur * OUT_CH + 2 * lane + 1, acc.y);
}

// ---------------- launch: SIZE-BASED input dispatch (order-proof) ----------------
extern "C" void kernel_launch(void* const* d_in, const int* in_sizes, int n_in,
                              void* d_out, int out_size) {
    const float* x = 0; const int* ei32 = 0; const int* b32 = 0;
    const float* Wlin = 0; const float* Wroot = 0;
    for (int i = 0; i < n_in; i++) {
        int s = in_sizes[i];
        if      (s == N_NODES * IN_CH)        x    = (const float*)d_in[i];
        else if (s == 2 * N_EDGES)            ei32 = (const int*)d_in[i];
        else if (s == N_NODES)                b32  = (const int*)d_in[i];
        else if (s == (MAX_DEG + 1) * IN_CH * OUT_CH) {
            if (!Wlin) Wlin = (const float*)d_in[i];
            else       Wroot = (const float*)d_in[i];
        }
    }
    if (!x)     x     = (const float*)d_in[0];
    if (!ei32)  ei32  = (const int*)d_in[1];
    if (!b32)   b32   = (const int*)d_in[2];
    if (!Wlin)  Wlin  = (const float*)d_in[3];
    if (!Wroot) Wroot = (const float*)d_in[4];
    float* out = (float*)d_out;

    fpnn_detect_kernel<<<1, 32>>>(ei32);
    fpnn_zero_kernel<<<(N_NODES + 255) / 256, 256>>>((float4*)out);
    fpnn_deg_kernel<<<(N_EDGES + 255) / 256, 256>>>(ei32);
    fpnn_scanA_kernel<<<NB, SCAN_B>>>();
    fpnn_scanB_kernel<<<1, SCAN_B>>>();
    fpnn_scanC_kernel<<<NB, SCAN_B>>>();
    fpnn_fill_kernel<<<(N_EDGES + 255) / 256, 256>>>(ei32);
    fpnn_bucket_kernel<<<(N_NODES + 255) / 256, 256>>>();
    fpnn_gemm_kernel<<<dim3(GX, MAX_DEG + 1), 256>>>((const float4*)x, Wlin, Wroot);
    fpnn_spool_kernel<<<(N_NODES / NODES_PER_WARP * 32 + 255) / 256, 256>>>(b32, out);
}

// round 9
// speedup vs baseline: 1.6444x; 1.3092x over previous
#include <cuda_runtime.h>
#include <cuda_bf16.h>
#include <cstdint>

#define N_NODES  200000
#define N_EDGES  800000
#define IN_CH    128
#define OUT_CH   64
#define MAX_DEG  4
#define N_GRAPHS 8192

// ---------------- scratch ----------------
__device__ int    fpnn_stride;                        // 1 = int32 inputs, 2 = int64
__device__ int    fpnn_cursor;
__device__ int    fpnn_deg[N_NODES];
__device__ int    fpnn_off[N_NODES];
__device__ int    fpnn_fill[N_NODES];
__device__ int    fpnn_csr[N_EDGES];
__device__ int    fpnn_cnt[MAX_DEG + 1];
__device__ int    fpnn_lists[(MAX_DEG + 1) * N_NODES];
__device__ float2 fpnn_pre2[(size_t)N_NODES * (OUT_CH / 2)];  // 51.2 MB

// ---------------- init: detect dtype + zero scratch + zero output ----------------
__global__ void fpnn_init_kernel(const int* __restrict__ ei32,
                                 float4* __restrict__ out4) {
    int i = blockIdx.x * blockDim.x + threadIdx.x;
    if (i == 0) {
        int nz = 0;
        for (int j = 0; j < 64; j++) nz |= ei32[2 * j + 1];
        fpnn_stride = (nz == 0) ? 2 : 1;
        fpnn_cursor = 0;
    }
    if (i < N_NODES) fpnn_deg[i] = 0;
    if (i <= MAX_DEG) fpnn_cnt[i] = 0;
    if (i < N_GRAPHS * OUT_CH / 4) out4[i] = make_float4(0.f, 0.f, 0.f, 0.f);
}

// ---------------- degree count ----------------
__global__ void fpnn_deg_kernel(const int* __restrict__ ei32) {
    int e = blockIdx.x * blockDim.x + threadIdx.x;
    if (e >= N_EDGES) return;
    int st = fpnn_stride;
    int dst = ei32[(size_t)st * (N_EDGES + e)];
    atomicAdd(&fpnn_deg[dst], 1);
}

// ---------------- offset alloc (cursor) + bucketize ----------------
__global__ void fpnn_alloc_kernel() {
    int n = blockIdx.x * blockDim.x + threadIdx.x;
    if (n >= N_NODES) return;
    int deg = fpnn_deg[n];
    fpnn_off[n] = atomicAdd(&fpnn_cursor, deg);
    fpnn_fill[n] = 0;
    int d = min(deg, MAX_DEG);
    int pos = atomicAdd(&fpnn_cnt[d], 1);
    fpnn_lists[d * N_NODES + pos] = n;
}

// ---------------- fill CSR ----------------
__global__ void fpnn_fill_kernel(const int* __restrict__ ei32) {
    int e = blockIdx.x * blockDim.x + threadIdx.x;
    if (e >= N_EDGES) return;
    int st = fpnn_stride;
    int src = ei32[(size_t)st * e];
    int dst = ei32[(size_t)st * (N_EDGES + e)];
    int pos = fpnn_off[dst] + atomicAdd(&fpnn_fill[dst], 1);
    fpnn_csr[pos] = src;
}

// ---------------- split-bf16 helpers ----------------
__device__ __forceinline__ unsigned fpnn_pack(float f0, float f1) {
    unsigned u0 = (unsigned)__bfloat16_as_ushort(__float2bfloat16_rn(f0));
    unsigned u1 = (unsigned)__bfloat16_as_ushort(__float2bfloat16_rn(f1));
    return (u1 << 16) | u0;   // little-endian: element k in low half
}
// bank-rotated smem index (uint2 elements, 32 per row)
__device__ __forceinline__ int fpnn_sw(int row, int khalf) {
    return row * 32 + ((khalf + row * 4) & 31);
}

#define FPNN_MMA(d, a0, a1, a2, a3, b0, b1)                                   \
    asm volatile(                                                             \
        "mma.sync.aligned.m16n8k16.row.col.f32.bf16.bf16.f32 "                \
        "{%0,%1,%2,%3},{%4,%5,%6,%7},{%8,%9},{%0,%1,%2,%3};"                  \
        : "+f"(d[0]), "+f"(d[1]), "+f"(d[2]), "+f"(d[3])                      \
        : "r"(a0), "r"(a1), "r"(a2), "r"(a3), "r"(b0), "r"(b1))

// ---------------- fused gather + split-bf16 tensor GEMM ----------------
// pre[n] = (sum_{src} x[src]) @ Wlin[d] + x[n] @ Wroot[d]
// Logical GEMM per bucket: A[count x 256] (agg||x) times B[256 x 64] ([Wlin;Wroot]).
// 3-term split: Ah·Bh + Ah·Bl + Al·Bh, fp32 accumulate.
// Tile 64 nodes x 64 ch; K in 4 chunks of 64. Block 256 thr = 8 warps (4 M x 2 N).
#define GX2 148
#define M_TILE 64
__global__ void __launch_bounds__(256)
fpnn_mma_kernel(const float4* __restrict__ x4,
                const float* __restrict__ Wlin,
                const float* __restrict__ Wroot) {
    __shared__ uint2 A_s[64 * 32];   // [node][khalf] {hi pair, lo pair} 16 KB
    __shared__ uint2 B_s[64 * 32];   // [ch][khalf]  {hi pair, lo pair} 16 KB

    int d = blockIdx.y;
    int count = fpnn_cnt[d];
    const int* list = fpnn_lists + d * N_NODES;
    const float* wl = Wlin  + (size_t)d * IN_CH * OUT_CH;
    const float* wr = Wroot + (size_t)d * IN_CH * OUT_CH;

    int tid = threadIdx.x;
    // A loader: thread = node slot (64) x k-sixteenth (4)
    int nl = tid >> 2, kt = tid & 3;
    // B loader: thread = channel (64) x k-sixteenth (4)
    int bn = tid & 63, bkg = tid >> 6;
    // compute: 8 warps: wm = warp&3 (16 rows), wn = warp>>2 (32 cols)
    int wid = tid >> 5, lane = tid & 31;
    int m0 = (wid & 3) * 16, n0 = (wid >> 2) * 32;
    int g = lane >> 2, t = lane & 3;

    for (int tile = blockIdx.x; tile * M_TILE < count; tile += GX2) {
        float acc[4][4];
#pragma unroll
        for (int i = 0; i < 4; i++)
#pragma unroll
            for (int j = 0; j < 4; j++) acc[i][j] = 0.f;

#pragma unroll
        for (int chunk = 0; chunk < 4; chunk++) {
            // ---- load A chunk (gathered agg for chunks 0,1; x for 2,3) ----
            float v[16];
#pragma unroll
            for (int j = 0; j < 16; j++) v[j] = 0.f;
            int nidx = tile * M_TILE + nl;
            if (nidx < count) {
                int n = list[nidx];
                if (chunk < 2) {
                    int deg = fpnn_deg[n];
                    int off = fpnn_off[n];
                    int cb = chunk * 16 + kt * 4;
                    for (int i = 0; i < deg; i++) {
                        int src = fpnn_csr[off + i];
                        const float4* r = x4 + (size_t)src * 32 + cb;
#pragma unroll
                        for (int q = 0; q < 4; q++) {
                            float4 a = r[q];
                            v[4*q+0] += a.x; v[4*q+1] += a.y;
                            v[4*q+2] += a.z; v[4*q+3] += a.w;
                        }
                    }
                } else {
                    const float4* r = x4 + (size_t)n * 32 + (chunk - 2) * 16 + kt * 4;
#pragma unroll
                    for (int q = 0; q < 4; q++) {
                        float4 a = r[q];
                        v[4*q+0] = a.x; v[4*q+1] = a.y;
                        v[4*q+2] = a.z; v[4*q+3] = a.w;
                    }
                }
            }
#pragma unroll
            for (int jj = 0; jj < 8; jj++) {
                float f0 = v[2*jj], f1 = v[2*jj+1];
                float h0 = __bfloat162float(__float2bfloat16_rn(f0));
                float h1 = __bfloat162float(__float2bfloat16_rn(f1));
                uint2 p;
                p.x = fpnn_pack(h0, h1);
                p.y = fpnn_pack(f0 - h0, f1 - h1);
                A_s[fpnn_sw(nl, kt * 8 + jj)] = p;
            }

            // ---- load B chunk: W[k][n] -> B_s[n][khalf], transposed ----
            {
                const float* wsrc = (chunk < 2) ? (wl + chunk * 64 * OUT_CH)
                                                : (wr + (chunk - 2) * 64 * OUT_CH);
#pragma unroll
                for (int jj = 0; jj < 8; jj++) {
                    int k0 = bkg * 16 + 2 * jj;
                    float f0 = wsrc[(size_t)k0 * OUT_CH + bn];
                    float f1 = wsrc[(size_t)(k0 + 1) * OUT_CH + bn];
                    float h0 = __bfloat162float(__float2bfloat16_rn(f0));
                    float h1 = __bfloat162float(__float2bfloat16_rn(f1));
                    uint2 p;
                    p.x = fpnn_pack(h0, h1);
                    p.y = fpnn_pack(f0 - h0, f1 - h1);
                    B_s[fpnn_sw(bn, bkg * 8 + jj)] = p;
                }
            }
            __syncthreads();

            // ---- mma over this chunk: 4 k-steps of 16 ----
#pragma unroll
            for (int ks = 0; ks < 4; ks++) {
                int kh = ks * 8 + t;
                uint2 A0 = A_s[fpnn_sw(m0 + g,     kh)];
                uint2 A1 = A_s[fpnn_sw(m0 + g + 8, kh)];
                uint2 A2 = A_s[fpnn_sw(m0 + g,     kh + 4)];
                uint2 A3 = A_s[fpnn_sw(m0 + g + 8, kh + 4)];
#pragma unroll
                for (int ns = 0; ns < 4; ns++) {
                    int n = n0 + ns * 8 + g;
                    uint2 B0 = B_s[fpnn_sw(n, kh)];
                    uint2 B1 = B_s[fpnn_sw(n, kh + 4)];
                    FPNN_MMA(acc[ns], A0.x, A1.x, A2.x, A3.x, B0.x, B1.x); // hi*hi
                    FPNN_MMA(acc[ns], A0.x, A1.x, A2.x, A3.x, B0.y, B1.y); // hi*lo
                    FPNN_MMA(acc[ns], A0.y, A1.y, A2.y, A3.y, B0.x, B1.x); // lo*hi
                }
            }
            __syncthreads();
        }

        // ---- store: C frag (g,2t),(g,2t+1) and (g+8,2t),(g+8,2t+1) ----
        int r0 = tile * M_TILE + m0 + g;
        int r1 = r0 + 8;
#pragma unroll
        for (int ns = 0; ns < 4; ns++) {
            int ncol_half = (n0 >> 1) + ns * 4 + t;   // float2 column index
            if (r0 < count) {
                int n = list[r0];
                fpnn_pre2[(size_t)n * 32 + ncol_half] = make_float2(acc[ns][0], acc[ns][1]);
            }
            if (r1 < count) {
                int n = list[r1];
                fpnn_pre2[(size_t)n * 32 + ncol_half] = make_float2(acc[ns][2], acc[ns][3]);
            }
        }
    }
}

// ---------------- fused relu + softmax + pool (warp per 8 sorted nodes) ---------
#define NODES_PER_WARP 8
__global__ void fpnn_spool_kernel(const int* __restrict__ b32,
                                  float* __restrict__ out) {
    int warp = (blockIdx.x * blockDim.x + threadIdx.x) >> 5;
    int lane = threadIdx.x & 31;
    int n0 = warp * NODES_PER_WARP;
    if (n0 >= N_NODES) return;
    int st = fpnn_stride;

    float2 acc = make_float2(0.f, 0.f);
    int gcur = b32[(size_t)st * n0];

#pragma unroll
    for (int i = 0; i < NODES_PER_WARP; i++) {
        int n = n0 + i;
        int g = b32[(size_t)st * n];
        if (g != gcur) {
            atomicAdd(out + (size_t)gcur * OUT_CH + 2 * lane,     acc.x);
            atomicAdd(out + (size_t)gcur * OUT_CH + 2 * lane + 1, acc.y);
            acc = make_float2(0.f, 0.f);
            gcur = g;
        }
        float2 v = fpnn_pre2[(size_t)n * 32 + lane];
        v.x = fmaxf(v.x, 0.f);
        v.y = fmaxf(v.y, 0.f);
        float m = fmaxf(v.x, v.y);
#pragma unroll
        for (int s = 16; s; s >>= 1) m = fmaxf(m, __shfl_xor_sync(0xffffffffu, m, s));
        float ex = __expf(v.x - m), ey = __expf(v.y - m);
        float s = ex + ey;
#pragma unroll
        for (int ss = 16; ss; ss >>= 1) s += __shfl_xor_sync(0xffffffffu, s, ss);
        float inv = 1.0f / s;
        acc.x += ex * inv;
        acc.y += ey * inv;
    }
    atomicAdd(out + (size_t)gcur * OUT_CH + 2 * lane,     acc.x);
    atomicAdd(out + (size_t)gcur * OUT_CH + 2 * lane + 1, acc.y);
}

// ---------------- launch: SIZE-BASED input dispatch (order-proof) ----------------
extern "C" void kernel_launch(void* const* d_in, const int* in_sizes, int n_in,
                              void* d_out, int out_size) {
    const float* x = 0; const int* ei32 = 0; const int* b32 = 0;
    const float* Wlin = 0; const float* Wroot = 0;
    for (int i = 0; i < n_in; i++) {
        int s = in_sizes[i];
        if      (s == N_NODES * IN_CH)        x    = (const float*)d_in[i];
        else if (s == 2 * N_EDGES)            ei32 = (const int*)d_in[i];
        else if (s == N_NODES)                b32  = (const int*)d_in[i];
        else if (s == (MAX_DEG + 1) * IN_CH * OUT_CH) {
            if (!Wlin) Wlin = (const float*)d_in[i];
            else       Wroot = (const float*)d_in[i];
        }
    }
    if (!x)     x     = (const float*)d_in[0];
    if (!ei32)  ei32  = (const int*)d_in[1];
    if (!b32)   b32   = (const int*)d_in[2];
    if (!Wlin)  Wlin  = (const float*)d_in[3];
    if (!Wroot) Wroot = (const float*)d_in[4];
    float* out = (float*)d_out;

    fpnn_init_kernel<<<(N_NODES + 255) / 256, 256>>>(ei32, (float4*)out);
    fpnn_deg_kernel<<<(N_EDGES + 255) / 256, 256>>>(ei32);
    fpnn_alloc_kernel<<<(N_NODES + 255) / 256, 256>>>();
    fpnn_fill_kernel<<<(N_EDGES + 255) / 256, 256>>>(ei32);
    fpnn_mma_kernel<<<dim3(GX2, MAX_DEG + 1), 256>>>((const float4*)x, Wlin, Wroot);
    fpnn_spool_kernel<<<(N_NODES / NODES_PER_WARP * 32 + 255) / 256, 256>>>(b32, out);
}